// round 5
// baseline (speedup 1.0000x reference)
#include <cuda_runtime.h>
#include <math.h>

#define BATCH 2048
#define TT    2048
#define HH    25
#define NPAIR 13

typedef unsigned long long u64;

// Packed f32x2 FMA (Blackwell, PTX-only form): two fp32 FMAs per instruction.
__device__ __forceinline__ u64 ffma2(u64 a, u64 b, u64 c) {
    u64 d; asm("fma.rn.f32x2 %0, %1, %2, %3;" : "=l"(d) : "l"(a), "l"(b), "l"(c)); return d;
}
__device__ __forceinline__ u64 pk2(float lo, float hi) {
    u64 r; asm("mov.b64 %0, {%1, %2};" : "=l"(r) : "f"(lo), "f"(hi)); return r;
}
__device__ __forceinline__ float2 upk2(u64 a) {
    float2 r; asm("mov.b64 {%0, %1}, %2;" : "=f"(r.x), "=f"(r.y) : "l"(a)); return r;
}
__device__ __forceinline__ float ex2a(float x) { float r; asm("ex2.approx.f32 %0, %1;" : "=f"(r) : "f"(x)); return r; }
__device__ __forceinline__ float rcpa(float x) { float r; asm("rcp.approx.f32 %0, %1;" : "=f"(r) : "f"(x)); return r; }

// Opaque shared-memory access (inline asm): sidesteps C++ aliasing between the
// f32 stores and b64 loads; "memory" clobber pins ordering around __syncwarp.
__device__ __forceinline__ u64 lds64(unsigned addr) {
    u64 r; asm volatile("ld.shared.b64 %0, [%1];" : "=l"(r) : "r"(addr) : "memory"); return r;
}
__device__ __forceinline__ void sts32(unsigned addr, float v) {
    asm volatile("st.shared.f32 [%0], %1;" :: "r"(addr), "f"(v) : "memory");
}

#define LOG2E 1.44269504088896340736f
__device__ __forceinline__ float sig_f(float x)  { return rcpa(1.0f + ex2a(-LOG2E * x)); }
__device__ __forceinline__ float tanh_f(float x) { return fmaf(2.0f, rcpa(1.0f + ex2a(-2.0f * LOG2E * x)), -1.0f); }

// One warp per sequence; lane j owns hidden unit j. Recurrent weights: 13
// packed f32x2 pairs per gate (52 u64 = 104 regs); pair 12's hi slot carries
// the gate bias, fed by a constant 1.0 parked in shared slot 25 of BOTH
// ping-pong buffers (per-step stores only touch slots 0..24, so it persists).
// Per step: 13 broadcast LDS.64 + 52 FFMA2, activations, one STS.32 per lane,
// one __syncwarp. Dense head for the PREVIOUS h overlaps the matvec (5-shuffle
// butterfly) and stores one step delayed. Register budget is deliberately
// trimmed (scalar x prefetch, scalar y store, no pair-packing shuffles) to fit
// under the launch_bounds cap WITHOUT spills — LDL spill reloads were the
// hidden bottleneck of all previous rounds (L1tex ~30-36%).
__global__ void __launch_bounds__(64, 7)
lstm_fused(const float* __restrict__ x,        // [B, T, 1]
           const float* __restrict__ w_ih,     // [4H, 1]
           const float* __restrict__ w_hh,     // [4H, H]
           const float* __restrict__ b_ih,     // [4H]
           const float* __restrict__ b_hh,     // [4H]
           const float* __restrict__ w_dense,  // [1, H]
           const float* __restrict__ b_dense,  // [1]
           float* __restrict__ out)            // [B, T, 1]
{
    __shared__ __align__(16) float hsh[2][2][32];   // [buf][warp][slot]

    const int w    = (int)(threadIdx.x >> 5);
    const int lane = (int)(threadIdx.x & 31u);
    const int gwarp = blockIdx.x * 2 + w;
    const int j = (lane < HH) ? lane : (HH - 1);

    // ---- per-lane weights: 4 gates x 13 packed pairs (104 regs) ----
    u64 W[4][NPAIR];
#pragma unroll
    for (int g = 0; g < 4; g++) {
        const float* row = w_hh + (g * HH + j) * HH;
#pragma unroll
        for (int p = 0; p < NPAIR - 1; p++)
            W[g][p] = pk2(row[2 * p], row[2 * p + 1]);
        W[g][NPAIR - 1] = pk2(row[24], b_ih[g * HH + j] + b_hh[g * HH + j]);
    }
    const float ui = w_ih[0 * HH + j], uf = w_ih[1 * HH + j];
    const float ug = w_ih[2 * HH + j], uo = w_ih[3 * HH + j];
    const float wd = (lane < HH) ? w_dense[lane] : 0.0f;
    const float bd = b_dense[0];

    const float* xrow = x   + (size_t)gwarp * TT;
    float*       orow = out + (size_t)gwarp * TT;

    const unsigned a0 = (unsigned)__cvta_generic_to_shared(&hsh[0][w][0]);
    const unsigned a1 = (unsigned)__cvta_generic_to_shared(&hsh[1][w][0]);

    // init both buffers: h=0 everywhere, slot 25 = 1.0 (permanent bias feed)
    {
        const float v = (lane == HH) ? 1.0f : 0.0f;
        hsh[0][w][lane] = v;
        hsh[1][w][lane] = v;
    }
    __syncwarp();

    float h = 0.0f, c = 0.0f;
    float xv = xrow[0];

#define STEP(GT, RA, WA)                                                      \
    {                                                                         \
        const int gt = (GT);                                                  \
        float xn = xrow[(gt < TT - 1) ? gt + 1 : gt];  /* prefetch next x */  \
        /* dense head for PREVIOUS h, overlapped with the matvec */           \
        float pr = h * wd;                                                    \
        pr += __shfl_xor_sync(0xffffffffu, pr, 16);                           \
        pr += __shfl_xor_sync(0xffffffffu, pr, 8);                            \
        pr += __shfl_xor_sync(0xffffffffu, pr, 4);                            \
        pr += __shfl_xor_sync(0xffffffffu, pr, 2);                            \
        pr += __shfl_xor_sync(0xffffffffu, pr, 1);                            \
        u64 ai = 0ull, af = 0ull, ag = 0ull, ao = 0ull;                       \
        _Pragma("unroll")                                                     \
        for (int p = 0; p < NPAIR; p++) {                                     \
            const u64 hpv = lds64((RA) + 8u * p);                             \
            ai = ffma2(hpv, W[0][p], ai);                                     \
            af = ffma2(hpv, W[1][p], af);                                     \
            ag = ffma2(hpv, W[2][p], ag);                                     \
            ao = ffma2(hpv, W[3][p], ao);                                     \
        }                                                                     \
        float2 vi = upk2(ai), vf = upk2(af), vg = upk2(ag), vo = upk2(ao);    \
        const float pi = fmaf(xv, ui, vi.x + vi.y);                           \
        const float pf = fmaf(xv, uf, vf.x + vf.y);                           \
        const float pg = fmaf(xv, ug, vg.x + vg.y);                           \
        const float po = fmaf(xv, uo, vo.x + vo.y);                           \
        const float gi = sig_f(pi);                                           \
        const float gf = sig_f(pf);                                           \
        const float gg = tanh_f(pg);                                          \
        const float go = sig_f(po);                                           \
        c = fmaf(gf, c, gi * gg);                                             \
        h = go * tanh_f(c);                                                   \
        if (lane < HH) sts32((WA) + 4u * lane, h);                            \
        if (lane == 0 && gt > 0) orow[gt - 1] = pr + bd;  /* y[t-1] */        \
        __syncwarp();                                                         \
        xv = xn;                                                              \
    }

#pragma unroll 1
    for (int t2 = 0; t2 < TT; t2 += 2) {
        STEP(t2,     a0, a1)    // read buf0, write buf1
        STEP(t2 + 1, a1, a0)    // read buf1, write buf0
    }
#undef STEP

    // final output element y[T-1]
    float pr = h * wd;
    pr += __shfl_xor_sync(0xffffffffu, pr, 16);
    pr += __shfl_xor_sync(0xffffffffu, pr, 8);
    pr += __shfl_xor_sync(0xffffffffu, pr, 4);
    pr += __shfl_xor_sync(0xffffffffu, pr, 2);
    pr += __shfl_xor_sync(0xffffffffu, pr, 1);
    if (lane == 0) orow[TT - 1] = pr + bd;
}

extern "C" void kernel_launch(void* const* d_in, const int* in_sizes, int n_in,
                              void* d_out, int out_size) {
    const float* x       = (const float*)d_in[0];
    const float* w_ih    = (const float*)d_in[1];
    const float* w_hh    = (const float*)d_in[2];
    const float* b_ih    = (const float*)d_in[3];
    const float* b_hh    = (const float*)d_in[4];
    const float* w_dense = (const float*)d_in[5];
    const float* b_dense = (const float*)d_in[6];
    float* out = (float*)d_out;

    // 1024 CTAs x 64 threads = one warp per sequence; 7 CTAs/SM -> 14 warps/SM,
    // single wave across 148 SMs.
    lstm_fused<<<BATCH / 2, 64>>>(x, w_ih, w_hh, b_ih, b_hh,
                                  w_dense, b_dense, out);
}